// round 8
// baseline (speedup 1.0000x reference)
#include <cuda_runtime.h>
#include <cstdint>

// Problem dims
#define HWX  16384      // 128*128
#define CHWX 1048576    // 64*128*128
#define TOTX 8388608    // 8*64*128*128

typedef unsigned long long ull;

// ---------------- device scratch (allocation-free rule: device globals) ----
__device__ __align__(16) float g_hs [TOTX];   // south row-scan, natural [b][c][h][w]
__device__ __align__(16) float g_hn [TOTX];   // north row-scan, natural
__device__ __align__(16) float g_hsT[TOTX];   // [b][c][w][h]
__device__ __align__(16) float g_hnT[TOTX];
__device__ __align__(16) float g_yT [TOTX];   // y transposed [b][c][w][h]
__device__ __align__(16) float g_col[4][TOTX];// per-direction col-scan output, [b][c][w][h]

// ---------------- f32x2 helpers -------------------------------------------
__device__ __forceinline__ void fma2(ull& acc, ull a, ull b) {
    asm("fma.rn.f32x2 %0, %1, %2, %0;" : "+l"(acc) : "l"(a), "l"(b));
}
__device__ __forceinline__ float2 unpk(ull v) {
    float2 f; asm("mov.b64 {%0, %1}, %2;" : "=f"(f.x), "=f"(f.y) : "l"(v)); return f;
}
__device__ __forceinline__ ull dal(double d) { return __double_as_longlong(d); }

// DSMEM scalar store into peer CTA's shared memory (cluster rank `rank`)
__device__ __forceinline__ void dsmem_store(float* laddr, int rank, float v) {
    uint32_t la = (uint32_t)__cvta_generic_to_shared(laddr);
    uint32_t ra;
    asm volatile("mapa.shared::cluster.u32 %0, %1, %2;" : "=r"(ra) : "r"(la), "r"(rank));
    asm volatile("st.shared::cluster.f32 [%0], %1;" :: "r"(ra), "f"(v) : "memory");
}

__device__ __forceinline__ float4 relu4(float4 v) {
    v.x = fmaxf(v.x, 0.f); v.y = fmaxf(v.y, 0.f);
    v.z = fmaxf(v.z, 0.f); v.w = fmaxf(v.w, 0.f);
    return v;
}

extern __shared__ __align__(16) float smdyn[];

// ===========================================================================
// Kernel 1: row scans (south dir=0, north dir=1).
// grid (8 w-tiles, 8 batch, 2 dirs), 128 threads.
// f32x2 lanes = out-channel pairs; x & h state duplicated in smem.
// Thread tile: 4 o x 2 w. Per c-iter: 8 FFMA2 + 4 LDS, 0 MOV.
// smem (floats): WaT 0, WbT 4096, sxD 8192 (2 x 64*36), shD 12800 (64*36),
//                ba 15104, bb 15168 -> 15232 fl = 60928 B
// ===========================================================================
#define RST 36   // padded row stride (floats) for duplicated tiles

__global__ void __launch_bounds__(128, 1) row_scan_kernel(
    const float* __restrict__ x, const float* __restrict__ y,
    const float* __restrict__ Wc, const float* __restrict__ bc)
{
    float* sWaT = smdyn;
    float* sWbT = smdyn + 4096;
    float* sxD0 = smdyn + 8192;     // + p*2304
    float* shD  = smdyn + 12800;
    float* sba  = smdyn + 15104;
    float* sbb  = smdyn + 15168;

    const int dir = blockIdx.z;          // 0 = south, 1 = north
    const int b   = blockIdx.y;
    const int w0  = blockIdx.x * 16;
    const int t   = threadIdx.x;

    const int ka = dir ? 8 : 0;
    const float* Wa = Wc + ka * 4096;
    const float* Wb = Wc + (ka + 1) * 4096;
    for (int idx = t; idx < 4096; idx += 128) {
        int o = idx >> 6, c = idx & 63;
        sWaT[c * 64 + o] = Wa[idx];
        sWbT[c * 64 + o] = Wb[idx];
    }
    if (t < 64) { sba[t] = bc[ka * 64 + t]; sbb[t] = bc[(ka + 1) * 64 + t]; }

    const float* xb = x + b * CHWX + w0;
    const float* yb = y + b * CHWX + w0;
    float* hb = (dir ? g_hn : g_hs) + b * CHWX + w0;

    const int lc = t >> 1;               // loader: channel
    const int lw = (t & 1) * 8;          // loader: 8 w per thread

    // boundary row init: natural out + duplicated state
    {
        const int r0 = dir ? 127 : 0;
        float4 v0 = *(const float4*)(xb + lc * HWX + r0 * 128 + lw);
        float4 v1 = *(const float4*)(xb + lc * HWX + r0 * 128 + lw + 4);
        if (dir) { v0 = relu4(v0); v1 = relu4(v1); }
        *(float4*)(hb + lc * HWX + r0 * 128 + lw)     = v0;
        *(float4*)(hb + lc * HWX + r0 * 128 + lw + 4) = v1;
        float* d = shD + lc * RST + 2 * lw;
        *(float4*)(d + 0)  = make_float4(v0.x, v0.x, v0.y, v0.y);
        *(float4*)(d + 4)  = make_float4(v0.z, v0.z, v0.w, v0.w);
        *(float4*)(d + 8)  = make_float4(v1.x, v1.x, v1.y, v1.y);
        *(float4*)(d + 12) = make_float4(v1.z, v1.z, v1.w, v1.w);
    }
    // x(step 1) -> sxD[1]; prefetch x(step 2) to regs
    float4 xr0, xr1;
    {
        const int r1 = dir ? 126 : 1;
        xr0 = *(const float4*)(xb + lc * HWX + r1 * 128 + lw);
        xr1 = *(const float4*)(xb + lc * HWX + r1 * 128 + lw + 4);
        float* d = sxD0 + 2304 + lc * RST + 2 * lw;
        *(float4*)(d + 0)  = make_float4(xr0.x, xr0.x, xr0.y, xr0.y);
        *(float4*)(d + 4)  = make_float4(xr0.z, xr0.z, xr0.w, xr0.w);
        *(float4*)(d + 8)  = make_float4(xr1.x, xr1.x, xr1.y, xr1.y);
        *(float4*)(d + 12) = make_float4(xr1.z, xr1.z, xr1.w, xr1.w);
        const int r2 = dir ? 125 : 2;
        xr0 = *(const float4*)(xb + lc * HWX + r2 * 128 + lw);
        xr1 = *(const float4*)(xb + lc * HWX + r2 * 128 + lw + 4);
    }

    const int o4 = (t >> 3) * 4;         // 4 out-channels (2 pairs)
    const int wq = (t & 7) * 2;          // 2 w positions

    for (int i = 1; i < 128; ++i) {
        const int p = i & 1;
        const float* sxP = sxD0 + p * 2304;
        const int r  = dir ? 127 - i : i;
        const int yr = dir ? r + 1 : r - 1;

        __syncthreads();   // orders: sxD[p] & shD writes from prev iter

        if (i < 127) {     // xr holds x(i+1): dup-store into sxD[1-p]
            float* d = sxD0 + (1 - p) * 2304 + lc * RST + 2 * lw;
            *(float4*)(d + 0)  = make_float4(xr0.x, xr0.x, xr0.y, xr0.y);
            *(float4*)(d + 4)  = make_float4(xr0.z, xr0.z, xr0.w, xr0.w);
            *(float4*)(d + 8)  = make_float4(xr1.x, xr1.x, xr1.y, xr1.y);
            *(float4*)(d + 12) = make_float4(xr1.z, xr1.z, xr1.w, xr1.w);
            if (i < 126) {
                const int rn = dir ? 127 - (i + 2) : (i + 2);
                xr0 = *(const float4*)(xb + lc * HWX + rn * 128 + lw);
                xr1 = *(const float4*)(xb + lc * HWX + rn * 128 + lw + 4);
            }
        }

        float2 yv[4];
        #pragma unroll
        for (int k = 0; k < 4; ++k)
            yv[k] = *(const float2*)(yb + (o4 + k) * HWX + yr * 128 + wq);

        ull aa[2][2], ab[2][2];
        aa[0][0]=aa[0][1]=aa[1][0]=aa[1][1]=0ULL;
        ab[0][0]=ab[0][1]=ab[1][0]=ab[1][1]=0ULL;

        #pragma unroll 8
        for (int c = 0; c < 64; ++c) {
            double2 xq = *(const double2*)(sxP + c * RST + 2 * wq);
            double2 hq = *(const double2*)(shD + c * RST + 2 * wq);
            double2 wa = *(const double2*)(sWaT + c * 64 + o4);
            double2 wb = *(const double2*)(sWbT + c * 64 + o4);
            ull x0 = dal(xq.x), x1 = dal(xq.y);
            ull h0 = dal(hq.x), h1 = dal(hq.y);
            ull wa0 = dal(wa.x), wa1 = dal(wa.y);
            ull wb0 = dal(wb.x), wb1 = dal(wb.y);
            fma2(aa[0][0], x0, wa0); fma2(aa[0][1], x1, wa0);
            fma2(aa[1][0], x0, wa1); fma2(aa[1][1], x1, wa1);
            fma2(ab[0][0], h0, wb0); fma2(ab[0][1], h1, wb0);
            fma2(ab[1][0], h0, wb1); fma2(ab[1][1], h1, wb1);
        }

        __syncthreads();   // all shD reads done before state overwrite

        #pragma unroll
        for (int k = 0; k < 4; ++k) {
            const int o = o4 + k, po = k >> 1;
            float2 u0 = unpk(aa[po][0]), u1 = unpk(aa[po][1]);
            float2 v0 = unpk(ab[po][0]), v1 = unpk(ab[po][1]);
            float Aw0 = (k & 1) ? u0.y : u0.x;
            float Aw1 = (k & 1) ? u1.y : u1.x;
            float Bw0 = (k & 1) ? v0.y : v0.x;
            float Bw1 = (k & 1) ? v1.y : v1.x;
            const float ba_ = sba[o], bb_ = sbb[o];
            float r0_ = fmaxf(Aw0 + ba_ + (Bw0 + bb_) * yv[k].x, 0.f);
            float r1_ = fmaxf(Aw1 + ba_ + (Bw1 + bb_) * yv[k].y, 0.f);
            *(float4*)(shD + o * RST + 2 * wq) = make_float4(r0_, r0_, r1_, r1_);
            *(float2*)(hb + o * HWX + r * 128 + wq) = make_float2(r0_, r1_);
        }
    }
}

// ===========================================================================
// Kernel 2: batched 128x128 transpose of last two dims.
// blockIdx.z: [0,512)=y->yT, [512,1024)=hs->hsT, [1024,1536)=hn->hnT
// ===========================================================================
__global__ void __launch_bounds__(256, 1) transpose3_kernel(const float* __restrict__ ysrc)
{
    __shared__ float tile[32][33];
    const int mode = blockIdx.z >> 9;
    const int n    = blockIdx.z & 511;
    const float* src = (mode == 0 ? ysrc : (mode == 1 ? g_hs : g_hn)) + n * HWX;
    float*       dst = (mode == 0 ? g_yT : (mode == 1 ? g_hsT : g_hnT)) + n * HWX;
    const int r0 = blockIdx.y * 32, c0 = blockIdx.x * 32;
    const int tx = threadIdx.x & 31, ty = (threadIdx.x >> 5) * 4;
    #pragma unroll
    for (int k = 0; k < 4; ++k) tile[ty + k][tx] = src[(r0 + ty + k) * 128 + c0 + tx];
    __syncthreads();
    #pragma unroll
    for (int k = 0; k < 4; ++k) dst[(c0 + ty + k) * 128 + r0 + tx] = tile[tx][ty + k];
}

// ===========================================================================
// Kernel 3: column scans, all 4 directions in one launch.
// grid (4 H-chunks [cluster 4], 8 batch, 4 dirs), 128 threads.
// f32x2 lanes = out-channel pairs; base & state duplicated in smem.
// Thread tile: 4 o x 4 h. Per c-iter: 24 FFMA2 + 7 LDS, 0 MOV.
// smem (floats): WtT 0, WaT 4096, WbT 8192, bsD 12288 (2 x 64*68),
//                cpD 20992 (64*68), sg 25344 (64*36), halo 27648 (2x64),
//                bt 27776, ba 27840, bb 27904 -> 27968 fl = 111872 B
// ===========================================================================
#define CST 68   // padded stride (floats) for duplicated col tiles
#define SGT 36   // padded stride for gated tile

__global__ void __launch_bounds__(128, 1) __cluster_dims__(4, 1, 1)
col_scan_kernel(const float* __restrict__ Wc, const float* __restrict__ bc,
                const float* __restrict__ gms)
{
    float* sWtT = smdyn;
    float* sWaT = smdyn + 4096;
    float* sWbT = smdyn + 8192;
    float* bsD0 = smdyn + 12288;    // + p*4352
    float* cpD  = smdyn + 20992;
    float* sg   = smdyn + 25344;
    float* halo = smdyn + 27648;
    float* sbt  = smdyn + 27776;
    float* sba  = smdyn + 27840;
    float* sbb  = smdyn + 27904;

    const int dir = blockIdx.z;     // 0 hse, 1 hsw, 2 hne, 3 hnw
    const int b   = blockIdx.y;
    const int cx  = blockIdx.x;     // cluster rank
    const int r0  = cx * 32;
    const int t   = threadIdx.x;

    int kt;
    if (dir == 0) kt = 2; else if (dir == 1) kt = 5; else if (dir == 2) kt = 10; else kt = 13;
    const int  wdir = (dir & 1) ? -1 : 1;
    const bool shup = (dir >= 2);
    const float gamma = gms[dir];

    for (int idx = t; idx < 4096; idx += 128) {
        int o = idx >> 6, c = idx & 63;
        sWtT[c * 64 + o] = Wc[kt * 4096 + idx];
        sWaT[c * 64 + o] = Wc[(kt + 1) * 4096 + idx];
        sWbT[c * 64 + o] = Wc[(kt + 2) * 4096 + idx];
    }
    if (t < 64) {
        sbt[t] = bc[kt * 64 + t];
        sba[t] = bc[(kt + 1) * 64 + t];
        sbb[t] = bc[(kt + 2) * 64 + t];
    }

    const float* baseb = ((dir < 2) ? g_hsT : g_hnT) + b * CHWX + r0;  // [c][w][h]
    const float* yTb   = g_yT + b * CHWX + r0;
    float*       outb  = g_col[dir] + b * CHWX + r0;

    const int lc = t >> 1;             // loader: channel
    const int lh = (t & 1) * 16;       // loader: 16 h per thread

    // init column j0: relu'd, duplicated state + output
    {
        const int j0 = (wdir > 0) ? 0 : 127;
        #pragma unroll
        for (int kk = 0; kk < 4; ++kk) {
            float4 v = relu4(*(const float4*)(baseb + lc * HWX + j0 * 128 + lh + kk * 4));
            *(float4*)(outb + lc * HWX + j0 * 128 + lh + kk * 4) = v;
            float* d = cpD + lc * CST + 2 * lh + kk * 8;
            *(float4*)(d + 0) = make_float4(v.x, v.x, v.y, v.y);
            *(float4*)(d + 4) = make_float4(v.z, v.z, v.w, v.w);
        }
    }
    // base(jj=1) -> bsD[1]; prefetch base(jj=2)
    float4 br[4];
    {
        const int j1 = (wdir > 0) ? 1 : 126;
        #pragma unroll
        for (int kk = 0; kk < 4; ++kk)
            br[kk] = *(const float4*)(baseb + lc * HWX + j1 * 128 + lh + kk * 4);
        float* d0 = bsD0 + 4352 + lc * CST + 2 * lh;
        #pragma unroll
        for (int kk = 0; kk < 4; ++kk) {
            *(float4*)(d0 + kk * 8 + 0) = make_float4(br[kk].x, br[kk].x, br[kk].y, br[kk].y);
            *(float4*)(d0 + kk * 8 + 4) = make_float4(br[kk].z, br[kk].z, br[kk].w, br[kk].w);
        }
        const int j2 = (wdir > 0) ? 2 : 125;
        #pragma unroll
        for (int kk = 0; kk < 4; ++kk)
            br[kk] = *(const float4*)(baseb + lc * HWX + j2 * 128 + lh + kk * 4);
    }

    const int o4 = (t >> 3) * 4;       // 4 out-channels (2 pairs)
    const int hq = (t & 7) * 4;        // 4 local h rows

    for (int jj = 1; jj < 128; ++jj) {
        const int p = jj & 1;
        const float* bsP = bsD0 + p * 4352;
        const int j  = (wdir > 0) ? jj : 127 - jj;
        const int yj = j - wdir;

        __syncthreads();   // orders bsD[p], cpD writes from prev iter

        if (jj < 127) {    // br holds base(jj+1): dup-store into bsD[1-p]
            float* d0 = bsD0 + (1 - p) * 4352 + lc * CST + 2 * lh;
            #pragma unroll
            for (int kk = 0; kk < 4; ++kk) {
                *(float4*)(d0 + kk * 8 + 0) = make_float4(br[kk].x, br[kk].x, br[kk].y, br[kk].y);
                *(float4*)(d0 + kk * 8 + 4) = make_float4(br[kk].z, br[kk].z, br[kk].w, br[kk].w);
            }
            if (jj < 126) {
                const int jn = (wdir > 0) ? jj + 2 : 125 - jj;
                #pragma unroll
                for (int kk = 0; kk < 4; ++kk)
                    br[kk] = *(const float4*)(baseb + lc * HWX + jn * 128 + lh + kk * 4);
            }
        }

        float yva[4][4];
        #pragma unroll
        for (int k = 0; k < 4; ++k) {
            float4 v = *(const float4*)(yTb + (o4 + k) * HWX + yj * 128 + hq);
            yva[k][0] = v.x; yva[k][1] = v.y; yva[k][2] = v.z; yva[k][3] = v.w;
        }

        ull aT[2][4], aA[2][4], aB[2][4];
        #pragma unroll
        for (int po = 0; po < 2; ++po)
            #pragma unroll
            for (int h = 0; h < 4; ++h) { aT[po][h] = 0ULL; aA[po][h] = 0ULL; aB[po][h] = 0ULL; }

        #pragma unroll 8
        for (int c = 0; c < 64; ++c) {
            double2 bq0 = *(const double2*)(bsP + c * CST + 2 * hq);
            double2 bq1 = *(const double2*)(bsP + c * CST + 2 * hq + 4);
            double2 pq0 = *(const double2*)(cpD + c * CST + 2 * hq);
            double2 pq1 = *(const double2*)(cpD + c * CST + 2 * hq + 4);
            double2 wt = *(const double2*)(sWtT + c * 64 + o4);
            double2 wa = *(const double2*)(sWaT + c * 64 + o4);
            double2 wb = *(const double2*)(sWbT + c * 64 + o4);
            ull bx[4] = { dal(bq0.x), dal(bq0.y), dal(bq1.x), dal(bq1.y) };
            ull px[4] = { dal(pq0.x), dal(pq0.y), dal(pq1.x), dal(pq1.y) };
            ull wtp[2] = { dal(wt.x), dal(wt.y) };
            ull wap[2] = { dal(wa.x), dal(wa.y) };
            ull wbp[2] = { dal(wb.x), dal(wb.y) };
            #pragma unroll
            for (int po = 0; po < 2; ++po)
                #pragma unroll
                for (int h = 0; h < 4; ++h) {
                    fma2(aT[po][h], px[h], wtp[po]);
                    fma2(aA[po][h], bx[h], wap[po]);
                    fma2(aB[po][h], px[h], wbp[po]);
                }
        }

        // gating
        float g[4][4];
        #pragma unroll
        for (int k = 0; k < 4; ++k) {
            const int po = k >> 1;
            const float bt_ = sbt[o4 + k];
            #pragma unroll
            for (int h = 0; h < 4; ++h) {
                float2 u = unpk(aT[po][h]);
                float tv = (k & 1) ? u.y : u.x;
                g[k][h] = (tv + bt_) * yva[k][h];
            }
            *(float4*)(sg + (o4 + k) * SGT + hq) =
                make_float4(g[k][0], g[k][1], g[k][2], g[k][3]);
        }

        // export boundary gated row to H-neighbor's halo (parity double-buffer)
        const int par = p * 64;
        if (!shup) {             // shift_down: my last local row -> cx+1
            if (hq == 28 && cx < 3) {
                #pragma unroll
                for (int k = 0; k < 4; ++k)
                    dsmem_store(halo + par + o4 + k, cx + 1, g[k][3]);
            }
        } else {                 // shift_up: my first local row -> cx-1
            if (hq == 0 && cx > 0) {
                #pragma unroll
                for (int k = 0; k < 4; ++k)
                    dsmem_store(halo + par + o4 + k, cx - 1, g[k][0]);
            }
        }
        asm volatile("barrier.cluster.arrive.aligned;" ::: "memory");
        asm volatile("barrier.cluster.wait.aligned;"   ::: "memory");

        #pragma unroll
        for (int k = 0; k < 4; ++k) {
            const int o = o4 + k, po = k >> 1;
            float s0, s1, s2, s3;
            if (!shup) {         // shifted[h] = gated[h-1], 0 at global h=0
                float m;
                if (hq > 0)      m = sg[o * SGT + hq - 1];
                else if (cx > 0) m = halo[par + o];
                else             m = 0.f;
                s0 = m; s1 = g[k][0]; s2 = g[k][1]; s3 = g[k][2];
            } else {             // shifted[h] = gated[h+1], 0 at global h=127
                float q_;
                if (hq < 28)     q_ = sg[o * SGT + hq + 4];
                else if (cx < 3) q_ = halo[par + o];
                else             q_ = 0.f;
                s0 = g[k][1]; s1 = g[k][2]; s2 = g[k][3]; s3 = q_;
            }
            float2 A0 = unpk(aA[po][0]), A1 = unpk(aA[po][1]);
            float2 A2 = unpk(aA[po][2]), A3 = unpk(aA[po][3]);
            float2 B0 = unpk(aB[po][0]), B1 = unpk(aB[po][1]);
            float2 B2 = unpk(aB[po][2]), B3 = unpk(aB[po][3]);
            float Av0 = (k & 1) ? A0.y : A0.x, Av1 = (k & 1) ? A1.y : A1.x;
            float Av2 = (k & 1) ? A2.y : A2.x, Av3 = (k & 1) ? A3.y : A3.x;
            float Bv0 = (k & 1) ? B0.y : B0.x, Bv1 = (k & 1) ? B1.y : B1.x;
            float Bv2 = (k & 1) ? B2.y : B2.x, Bv3 = (k & 1) ? B3.y : B3.x;
            const float ba_ = sba[o], bb_ = sbb[o];
            float4 cres;
            cres.x = fmaxf(Av0 + ba_ + (Bv0 + bb_) * yva[k][0] + gamma * s0, 0.f);
            cres.y = fmaxf(Av1 + ba_ + (Bv1 + bb_) * yva[k][1] + gamma * s1, 0.f);
            cres.z = fmaxf(Av2 + ba_ + (Bv2 + bb_) * yva[k][2] + gamma * s2, 0.f);
            cres.w = fmaxf(Av3 + ba_ + (Bv3 + bb_) * yva[k][3] + gamma * s3, 0.f);
            float* d = cpD + o * CST + 2 * hq;
            *(float4*)(d + 0) = make_float4(cres.x, cres.x, cres.y, cres.y);
            *(float4*)(d + 4) = make_float4(cres.z, cres.z, cres.w, cres.w);
            *(float4*)(outb + o * HWX + j * 128 + hq) = cres;
        }
    }
}

// ===========================================================================
// Kernel 4: sum four direction buffers ([b][c][w][h]) and transpose to d_out.
// ===========================================================================
__global__ void __launch_bounds__(256, 1) sum_transpose_kernel(float* __restrict__ out)
{
    __shared__ float tile[32][33];
    const int n  = blockIdx.z;                 // b*64 + c
    const int w0 = blockIdx.y * 32, h0 = blockIdx.x * 32;
    const int tx = threadIdx.x & 31, ty = (threadIdx.x >> 5) * 4;
    const float* s0 = g_col[0] + n * HWX;
    const float* s1 = g_col[1] + n * HWX;
    const float* s2 = g_col[2] + n * HWX;
    const float* s3 = g_col[3] + n * HWX;
    #pragma unroll
    for (int k = 0; k < 4; ++k) {
        int idx = (w0 + ty + k) * 128 + h0 + tx;
        tile[ty + k][tx] = s0[idx] + s1[idx] + s2[idx] + s3[idx];
    }
    __syncthreads();
    float* d = out + n * HWX;
    #pragma unroll
    for (int k = 0; k < 4; ++k)
        d[(h0 + ty + k) * 128 + w0 + tx] = tile[tx][ty + k];
}

// ===========================================================================
extern "C" void kernel_launch(void* const* d_in, const int* in_sizes, int n_in,
                              void* d_out, int out_size)
{
    const float* x  = (const float*)d_in[0];
    const float* y  = (const float*)d_in[1];
    const float* Wc = (const float*)d_in[2];
    const float* bc = (const float*)d_in[3];
    const float* gm = (const float*)d_in[4];
    float* out = (float*)d_out;

    const int ROWSMEM = 15232 * 4;  // 60928 B
    const int COLSMEM = 27968 * 4;  // 111872 B
    cudaFuncSetAttribute(row_scan_kernel,
                         cudaFuncAttributeMaxDynamicSharedMemorySize, ROWSMEM);
    cudaFuncSetAttribute(col_scan_kernel,
                         cudaFuncAttributeMaxDynamicSharedMemorySize, COLSMEM);

    row_scan_kernel<<<dim3(8, 8, 2), 128, ROWSMEM>>>(x, y, Wc, bc);
    transpose3_kernel<<<dim3(4, 4, 1536), 256>>>(y);
    col_scan_kernel<<<dim3(4, 8, 4), 128, COLSMEM>>>(Wc, bc, gm);
    sum_transpose_kernel<<<dim3(4, 4, 512), 256>>>(out);

    (void)in_sizes; (void)n_in; (void)out_size;
}

// round 9
// speedup vs baseline: 1.3850x; 1.3850x over previous
#include <cuda_runtime.h>
#include <cstdint>

// Problem dims
#define HWX  16384      // 128*128
#define CHWX 1048576    // 64*128*128
#define TOTX 8388608    // 8*64*128*128

typedef unsigned long long ull;

// ---------------- device scratch (allocation-free rule: device globals) ----
__device__ __align__(16) float g_hs [TOTX];   // south row-scan, natural [b][c][h][w]
__device__ __align__(16) float g_hn [TOTX];   // north row-scan, natural
__device__ __align__(16) float g_hsT[TOTX];   // [b][c][w][h]
__device__ __align__(16) float g_hnT[TOTX];
__device__ __align__(16) float g_yT [TOTX];   // y transposed [b][c][w][h]
__device__ __align__(16) float g_col[4][TOTX];// per-direction col-scan output, [b][c][w][h]

// ---------------- f32x2 helpers -------------------------------------------
__device__ __forceinline__ ull dup2(float w) {
    ull r; asm("mov.b64 %0, {%1, %1};" : "=l"(r) : "f"(w)); return r;
}
__device__ __forceinline__ void fma2(ull& acc, ull a, ull b) {
    asm("fma.rn.f32x2 %0, %1, %2, %0;" : "+l"(acc) : "l"(a), "l"(b));
}
__device__ __forceinline__ float2 unpk(ull v) {
    float2 f; asm("mov.b64 {%0, %1}, %2;" : "=f"(f.x), "=f"(f.y) : "l"(v)); return f;
}
__device__ __forceinline__ ull dal(double d) { return __double_as_longlong(d); }

// ---------------- cp.async helpers ----------------------------------------
__device__ __forceinline__ void cpasync16(void* s, const void* g) {
    uint32_t sa = (uint32_t)__cvta_generic_to_shared(s);
    asm volatile("cp.async.ca.shared.global [%0], [%1], 16;" :: "r"(sa), "l"(g) : "memory");
}
__device__ __forceinline__ void cpcommit() { asm volatile("cp.async.commit_group;" ::: "memory"); }
__device__ __forceinline__ void cpwait0()  { asm volatile("cp.async.wait_group 0;"  ::: "memory"); }

// DSMEM scalar store into peer CTA's shared memory (cluster rank `rank`)
__device__ __forceinline__ void dsmem_store(float* laddr, int rank, float v) {
    uint32_t la = (uint32_t)__cvta_generic_to_shared(laddr);
    uint32_t ra;
    asm volatile("mapa.shared::cluster.u32 %0, %1, %2;" : "=r"(ra) : "r"(la), "r"(rank));
    asm volatile("st.shared::cluster.f32 [%0], %1;" :: "r"(ra), "f"(v) : "memory");
}

__device__ __forceinline__ float4 relu4(float4 v) {
    v.x = fmaxf(v.x, 0.f); v.y = fmaxf(v.y, 0.f);
    v.z = fmaxf(v.z, 0.f); v.w = fmaxf(v.w, 0.f);
    return v;
}

extern __shared__ __align__(16) float smdyn[];

// ===========================================================================
// Kernel 1: row scans (south dir=0, north dir=1).
// grid (8 w-tiles, 8 batch, 2 dirs), 256 threads (2 warps/SMSP).
// Thread tile: 2 out-channels x 2 w (one f32x2 pair). Weights [c][o] float2.
// x/y tiles double-buffered via cp.async.
// smem layout (floats): WaT 0, WbT 4096, sx 8192(2x1024), sy 10240(2x1024),
//                       sh 12288, ba 13312, bb 13376  -> 13440 fl = 53760 B
// ===========================================================================
__global__ void __launch_bounds__(256, 1) row_scan_kernel(
    const float* __restrict__ x, const float* __restrict__ y,
    const float* __restrict__ Wc, const float* __restrict__ bc)
{
    float* sWaT = smdyn;
    float* sWbT = smdyn + 4096;
    float* sx   = smdyn + 8192;
    float* sy   = smdyn + 10240;
    float* sh   = smdyn + 12288;
    float* sba  = smdyn + 13312;
    float* sbb  = smdyn + 13376;

    const int dir = blockIdx.z;          // 0 = south, 1 = north
    const int b   = blockIdx.y;
    const int w0  = blockIdx.x * 16;
    const int t   = threadIdx.x;

    const int ka = dir ? 8 : 0;
    const float* Wa = Wc + ka * 4096;
    const float* Wb = Wc + (ka + 1) * 4096;
    for (int idx = t; idx < 4096; idx += 256) {
        int o = idx >> 6, c = idx & 63;
        sWaT[c * 64 + o] = Wa[idx];
        sWbT[c * 64 + o] = Wb[idx];
    }
    if (t < 64) { sba[t] = bc[ka * 64 + t]; sbb[t] = bc[(ka + 1) * 64 + t]; }

    const float* xb = x + b * CHWX + w0;
    const float* yb = y + b * CHWX + w0;
    float* hb = (dir ? g_hn : g_hs) + b * CHWX + w0;

    // boundary row init: 4 floats per thread
    {
        const int r0 = dir ? 127 : 0;
        const int c  = t >> 2;
        const int wv = (t & 3) * 4;
        float4 v = *(const float4*)(xb + c * HWX + r0 * 128 + wv);
        if (dir) v = relu4(v);
        *(float4*)(sh + c * 16 + wv) = v;
        *(float4*)(hb + c * HWX + r0 * 128 + wv) = v;
    }
    // prefetch step 1 tiles into parity-1 buffers (256 cp16 per tile)
    {
        const int r2  = dir ? 126 : 1;
        const int yr2 = dir ? 127 : 0;
        const int c = t >> 2, w = (t & 3) * 4;
        cpasync16(sx + 1024 + c * 16 + w, xb + c * HWX + r2  * 128 + w);
        cpasync16(sy + 1024 + c * 16 + w, yb + c * HWX + yr2 * 128 + w);
        cpcommit();
    }

    const int o2 = (t >> 3) * 2;         // 2 out-channels
    const int wq = (t & 7) * 2;          // one w pair

    for (int i = 1; i < 128; ++i) {
        const int p = i & 1;
        const float* sxP = sx + p * 1024;
        const float* syP = sy + p * 1024;
        const int r = dir ? 127 - i : i;

        cpwait0();
        __syncthreads();

        if (i < 127) {
            const int r2  = dir ? 127 - (i + 1) : (i + 1);
            const int yr2 = dir ? r2 + 1 : r2 - 1;
            float* sxN = sx + (1 - p) * 1024;
            float* syN = sy + (1 - p) * 1024;
            const int c = t >> 2, w = (t & 3) * 4;
            cpasync16(sxN + c * 16 + w, xb + c * HWX + r2  * 128 + w);
            cpasync16(syN + c * 16 + w, yb + c * HWX + yr2 * 128 + w);
            cpcommit();
        }

        ull aa[2], ab[2];
        aa[0] = aa[1] = 0ULL;
        ab[0] = ab[1] = 0ULL;

        #pragma unroll 8
        for (int c = 0; c < 64; ++c) {
            ull xv = dal(*(const double*)(sxP + c * 16 + wq));
            ull hv = dal(*(const double*)(sh  + c * 16 + wq));
            float2 wa = *(const float2*)(sWaT + c * 64 + o2);
            float2 wb = *(const float2*)(sWbT + c * 64 + o2);
            fma2(aa[0], xv, dup2(wa.x));
            fma2(aa[1], xv, dup2(wa.y));
            fma2(ab[0], hv, dup2(wb.x));
            fma2(ab[1], hv, dup2(wb.y));
        }

        float2 res[2];
        #pragma unroll
        for (int k = 0; k < 2; ++k) {
            const int o = o2 + k;
            float2 A  = unpk(aa[k]);
            float2 Bv = unpk(ab[k]);
            float2 yv = *(const float2*)(syP + o * 16 + wq);
            const float ba_ = sba[o], bb_ = sbb[o];
            res[k].x = fmaxf(A.x + ba_ + (Bv.x + bb_) * yv.x, 0.f);
            res[k].y = fmaxf(A.y + ba_ + (Bv.y + bb_) * yv.y, 0.f);
        }
        __syncthreads();
        #pragma unroll
        for (int k = 0; k < 2; ++k) {
            const int o = o2 + k;
            *(float2*)(sh + o * 16 + wq) = res[k];
            *(float2*)(hb + o * HWX + r * 128 + wq) = res[k];
        }
    }
}

// ===========================================================================
// Kernel 2: batched 128x128 transpose of last two dims.
// blockIdx.z: [0,512)=y->yT, [512,1024)=hs->hsT, [1024,1536)=hn->hnT
// ===========================================================================
__global__ void __launch_bounds__(256, 1) transpose3_kernel(const float* __restrict__ ysrc)
{
    __shared__ float tile[32][33];
    const int mode = blockIdx.z >> 9;
    const int n    = blockIdx.z & 511;
    const float* src = (mode == 0 ? ysrc : (mode == 1 ? g_hs : g_hn)) + n * HWX;
    float*       dst = (mode == 0 ? g_yT : (mode == 1 ? g_hsT : g_hnT)) + n * HWX;
    const int r0 = blockIdx.y * 32, c0 = blockIdx.x * 32;
    const int tx = threadIdx.x & 31, ty = (threadIdx.x >> 5) * 4;
    #pragma unroll
    for (int k = 0; k < 4; ++k) tile[ty + k][tx] = src[(r0 + ty + k) * 128 + c0 + tx];
    __syncthreads();
    #pragma unroll
    for (int k = 0; k < 4; ++k) dst[(c0 + ty + k) * 128 + r0 + tx] = tile[tx][ty + k];
}

// ===========================================================================
// Kernel 3: column scans, all 4 directions in one launch.
// grid (4 H-chunks [cluster 4], 8 batch, 4 dirs), 256 threads (2 warps/SMSP).
// Thread tile: 2 out-channels x 4 h (two f32x2 pairs). f32x2 mainloop,
// scalar epilogue. Base column double-buffered via cp.async; y prefetched
// to registers. One gated boundary row exchanged per step via DSMEM.
// smem (floats): WtT 0, WaT 4096, WbT 8192, bs 12288(2x2048), cp 16384,
//                sg 18432, halo 20480(2x64), bt 20608, ba 20672, bb 20736
//                -> 20800 fl = 83200 B
// ===========================================================================
__global__ void __launch_bounds__(256, 1) __cluster_dims__(4, 1, 1)
col_scan_kernel(const float* __restrict__ Wc, const float* __restrict__ bc,
                const float* __restrict__ gms)
{
    float* sWtT = smdyn;
    float* sWaT = smdyn + 4096;
    float* sWbT = smdyn + 8192;
    float* bsB  = smdyn + 12288;
    float* cp   = smdyn + 16384;
    float* sg   = smdyn + 18432;
    float* halo = smdyn + 20480;
    float* sbt  = smdyn + 20608;
    float* sba  = smdyn + 20672;
    float* sbb  = smdyn + 20736;

    const int dir = blockIdx.z;     // 0 hse, 1 hsw, 2 hne, 3 hnw
    const int b   = blockIdx.y;
    const int cx  = blockIdx.x;     // cluster rank
    const int r0  = cx * 32;
    const int t   = threadIdx.x;

    int kt;
    if (dir == 0) kt = 2; else if (dir == 1) kt = 5; else if (dir == 2) kt = 10; else kt = 13;
    const int  wdir = (dir & 1) ? -1 : 1;
    const bool shup = (dir >= 2);
    const float gamma = gms[dir];

    for (int idx = t; idx < 4096; idx += 256) {
        int o = idx >> 6, c = idx & 63;
        sWtT[c * 64 + o] = Wc[kt * 4096 + idx];
        sWaT[c * 64 + o] = Wc[(kt + 1) * 4096 + idx];
        sWbT[c * 64 + o] = Wc[(kt + 2) * 4096 + idx];
    }
    if (t < 64) {
        sbt[t] = bc[kt * 64 + t];
        sba[t] = bc[(kt + 1) * 64 + t];
        sbb[t] = bc[(kt + 2) * 64 + t];
    }

    const float* baseb = ((dir < 2) ? g_hsT : g_hnT) + b * CHWX + r0;  // [c][w][h]
    const float* yTb   = g_yT + b * CHWX + r0;
    float*       outb  = g_col[dir] + b * CHWX + r0;

    // init column j0: 8 floats per thread
    {
        const int j0 = (wdir > 0) ? 0 : 127;
        const int c  = t >> 2;
        const int h0 = (t & 3) * 8;
        #pragma unroll
        for (int kk = 0; kk < 2; ++kk) {
            float4 v = relu4(*(const float4*)(baseb + c * HWX + j0 * 128 + h0 + kk * 4));
            *(float4*)(cp + c * 32 + h0 + kk * 4) = v;
            *(float4*)(outb + c * HWX + j0 * 128 + h0 + kk * 4) = v;
        }
    }
    // prefetch base column for step 1 into parity-1 buffer (512 cp16)
    {
        const int j1 = (wdir > 0) ? 1 : 126;
        float* nb = bsB + 2048;
        #pragma unroll
        for (int k = 0; k < 2; ++k) {
            int q = t + 256 * k;
            int c = q >> 3, h = (q & 7) * 4;
            cpasync16(nb + c * 32 + h, baseb + c * HWX + j1 * 128 + h);
        }
        cpcommit();
    }

    const int o2 = (t >> 3) * 2;       // 2 out-channels
    const int hq = (t & 7) * 4;        // 4 local h rows

    for (int jj = 1; jj < 128; ++jj) {
        const int p = jj & 1;
        const float* bsP = bsB + p * 2048;
        const int j  = (wdir > 0) ? jj : 127 - jj;
        const int yj = j - wdir;

        cpwait0();
        __syncthreads();

        if (jj < 127) {
            const int j2 = (wdir > 0) ? jj + 1 : 126 - jj;
            float* nb = bsB + (1 - p) * 2048;
            #pragma unroll
            for (int k = 0; k < 2; ++k) {
                int q = t + 256 * k;
                int c = q >> 3, h = (q & 7) * 4;
                cpasync16(nb + c * 32 + h, baseb + c * HWX + j2 * 128 + h);
            }
            cpcommit();
        }

        float4 yv[2];
        #pragma unroll
        for (int k = 0; k < 2; ++k)
            yv[k] = *(const float4*)(yTb + (o2 + k) * HWX + yj * 128 + hq);

        ull aT[2][2], aA[2][2], aB[2][2];
        #pragma unroll
        for (int k = 0; k < 2; ++k) {
            aT[k][0] = aT[k][1] = 0ULL;
            aA[k][0] = aA[k][1] = 0ULL;
            aB[k][0] = aB[k][1] = 0ULL;
        }

        #pragma unroll 8
        for (int c = 0; c < 64; ++c) {
            double2 bv = *(const double2*)(bsP + c * 32 + hq);
            double2 pv = *(const double2*)(cp  + c * 32 + hq);
            ull b0 = dal(bv.x), b1 = dal(bv.y);
            ull p0 = dal(pv.x), p1 = dal(pv.y);
            float2 wt = *(const float2*)(sWtT + c * 64 + o2);
            float2 wa = *(const float2*)(sWaT + c * 64 + o2);
            float2 wb = *(const float2*)(sWbT + c * 64 + o2);
            ull w;
            w = dup2(wt.x); fma2(aT[0][0], p0, w); fma2(aT[0][1], p1, w);
            w = dup2(wt.y); fma2(aT[1][0], p0, w); fma2(aT[1][1], p1, w);
            w = dup2(wa.x); fma2(aA[0][0], b0, w); fma2(aA[0][1], b1, w);
            w = dup2(wa.y); fma2(aA[1][0], b0, w); fma2(aA[1][1], b1, w);
            w = dup2(wb.x); fma2(aB[0][0], p0, w); fma2(aB[0][1], p1, w);
            w = dup2(wb.y); fma2(aB[1][0], p0, w); fma2(aB[1][1], p1, w);
        }

        // gating (scalar epilogue)
        float g[2][4];
        #pragma unroll
        for (int k = 0; k < 2; ++k) {
            float2 t0 = unpk(aT[k][0]), t1 = unpk(aT[k][1]);
            const float bt_ = sbt[o2 + k];
            g[k][0] = (t0.x + bt_) * yv[k].x;
            g[k][1] = (t0.y + bt_) * yv[k].y;
            g[k][2] = (t1.x + bt_) * yv[k].z;
            g[k][3] = (t1.y + bt_) * yv[k].w;
            *(float4*)(sg + (o2 + k) * 32 + hq) =
                make_float4(g[k][0], g[k][1], g[k][2], g[k][3]);
        }

        // export boundary gated row to H-neighbor's halo (parity double-buffer)
        const int par = p * 64;
        if (!shup) {             // shift_down: my last local row -> cx+1
            if (hq == 28 && cx < 3) {
                #pragma unroll
                for (int k = 0; k < 2; ++k)
                    dsmem_store(halo + par + o2 + k, cx + 1, g[k][3]);
            }
        } else {                 // shift_up: my first local row -> cx-1
            if (hq == 0 && cx > 0) {
                #pragma unroll
                for (int k = 0; k < 2; ++k)
                    dsmem_store(halo + par + o2 + k, cx - 1, g[k][0]);
            }
        }
        asm volatile("barrier.cluster.arrive.aligned;" ::: "memory");
        asm volatile("barrier.cluster.wait.aligned;"   ::: "memory");

        #pragma unroll
        for (int k = 0; k < 2; ++k) {
            const int o = o2 + k;
            float s0, s1, s2, s3;
            if (!shup) {         // shifted[h] = gated[h-1], 0 at global h=0
                float m;
                if (hq > 0)      m = sg[o * 32 + hq - 1];
                else if (cx > 0) m = halo[par + o];
                else             m = 0.f;
                s0 = m; s1 = g[k][0]; s2 = g[k][1]; s3 = g[k][2];
            } else {             // shifted[h] = gated[h+1], 0 at global h=127
                float q_;
                if (hq < 28)     q_ = sg[o * 32 + hq + 4];
                else if (cx < 3) q_ = halo[par + o];
                else             q_ = 0.f;
                s0 = g[k][1]; s1 = g[k][2]; s2 = g[k][3]; s3 = q_;
            }
            float2 A0 = unpk(aA[k][0]), A1 = unpk(aA[k][1]);
            float2 B0 = unpk(aB[k][0]), B1 = unpk(aB[k][1]);
            const float ba_ = sba[o], bb_ = sbb[o];
            float4 cres;
            cres.x = fmaxf(A0.x + ba_ + (B0.x + bb_) * yv[k].x + gamma * s0, 0.f);
            cres.y = fmaxf(A0.y + ba_ + (B0.y + bb_) * yv[k].y + gamma * s1, 0.f);
            cres.z = fmaxf(A1.x + ba_ + (B1.x + bb_) * yv[k].z + gamma * s2, 0.f);
            cres.w = fmaxf(A1.y + ba_ + (B1.y + bb_) * yv[k].w + gamma * s3, 0.f);
            *(float4*)(cp + o * 32 + hq) = cres;
            *(float4*)(outb + o * HWX + j * 128 + hq) = cres;
        }
    }
}

// ===========================================================================
// Kernel 4: sum four direction buffers ([b][c][w][h]) and transpose to d_out.
// ===========================================================================
__global__ void __launch_bounds__(256, 1) sum_transpose_kernel(float* __restrict__ out)
{
    __shared__ float tile[32][33];
    const int n  = blockIdx.z;                 // b*64 + c
    const int w0 = blockIdx.y * 32, h0 = blockIdx.x * 32;
    const int tx = threadIdx.x & 31, ty = (threadIdx.x >> 5) * 4;
    const float* s0 = g_col[0] + n * HWX;
    const float* s1 = g_col[1] + n * HWX;
    const float* s2 = g_col[2] + n * HWX;
    const float* s3 = g_col[3] + n * HWX;
    #pragma unroll
    for (int k = 0; k < 4; ++k) {
        int idx = (w0 + ty + k) * 128 + h0 + tx;
        tile[ty + k][tx] = s0[idx] + s1[idx] + s2[idx] + s3[idx];
    }
    __syncthreads();
    float* d = out + n * HWX;
    #pragma unroll
    for (int k = 0; k < 4; ++k)
        d[(h0 + ty + k) * 128 + w0 + tx] = tile[tx][ty + k];
}

// ===========================================================================
extern "C" void kernel_launch(void* const* d_in, const int* in_sizes, int n_in,
                              void* d_out, int out_size)
{
    const float* x  = (const float*)d_in[0];
    const float* y  = (const float*)d_in[1];
    const float* Wc = (const float*)d_in[2];
    const float* bc = (const float*)d_in[3];
    const float* gm = (const float*)d_in[4];
    float* out = (float*)d_out;

    const int ROWSMEM = 13440 * 4;  // 53760 B
    const int COLSMEM = 20800 * 4;  // 83200 B
    cudaFuncSetAttribute(row_scan_kernel,
                         cudaFuncAttributeMaxDynamicSharedMemorySize, ROWSMEM);
    cudaFuncSetAttribute(col_scan_kernel,
                         cudaFuncAttributeMaxDynamicSharedMemorySize, COLSMEM);

    row_scan_kernel<<<dim3(8, 8, 2), 256, ROWSMEM>>>(x, y, Wc, bc);
    transpose3_kernel<<<dim3(4, 4, 1536), 256>>>(y);
    col_scan_kernel<<<dim3(4, 8, 4), 256, COLSMEM>>>(Wc, bc, gm);
    sum_transpose_kernel<<<dim3(4, 4, 512), 256>>>(out);

    (void)in_sizes; (void)n_in; (void)out_size;
}